// round 13
// baseline (speedup 1.0000x reference)
#include <cuda_runtime.h>
#include <cuda_fp16.h>
#include <cstdint>

// Problem constants
namespace {
constexpr int kB   = 2;
constexpr int kS   = 2048;
constexpr int kDin = 2048;
constexpr int kNH  = 32;
constexpr int kNKV = 8;
constexpr int kHD  = 64;
constexpr int kDout = 2048;           // kNH * kHD
constexpr int kM   = kB * kS;         // 4096 rows
constexpr int kKV  = kNKV * kHD;      // 512
// combined scale: (1/sqrt(64)) * log2(e) so softmax uses raw EX2
constexpr float kQScale = 0.18033688f;
}

// Scratch (static device arrays; cudaMalloc is forbidden)
__device__ __half g_Q[kM * kDout];       // 16 MB (pre-scaled fp16, [b,h,s,d])
__device__ __half g_Kh[kM * kKV];        // 4 MB (fp16, [b,g,s,d])
__device__ __half g_Vh[kM * kKV];        // 4 MB (fp16, TRANSPOSED [b,g,d,s])
__device__ __half g_Ctx[kM * kDout];     // 16 MB (fp16)
__device__ __half g_xh[kM * kDin];       // 16 MB (fp16 inputs/weights)
__device__ __half g_Wqh[kDout * kDin];   // 8 MB
__device__ __half g_Wkh[kKV * kDin];     // 2 MB
__device__ __half g_Wvh[kKV * kDin];     // 2 MB
__device__ __half g_Woh[kDin * kDout];   // 8 MB

__device__ __forceinline__ float fexp2(float x) {
  float y;
  asm("ex2.approx.ftz.f32 %0, %1;" : "=f"(y) : "f"(x));
  return y;
}

__device__ __forceinline__ void cp_async16(uint32_t smem_addr, const void* gptr) {
  asm volatile("cp.async.cg.shared.global [%0], [%1], 16;" :: "r"(smem_addr), "l"(gptr));
}

// fp16 tensor-core MMA: m16n8k16, fp32 accumulate
__device__ __forceinline__ void mma_f16(float* c, const uint32_t* a, const uint32_t* b) {
  asm volatile(
      "mma.sync.aligned.m16n8k16.row.col.f32.f16.f16.f32 "
      "{%0,%1,%2,%3}, {%4,%5,%6,%7}, {%8,%9}, {%0,%1,%2,%3};"
      : "+f"(c[0]), "+f"(c[1]), "+f"(c[2]), "+f"(c[3])
      : "r"(a[0]), "r"(a[1]), "r"(a[2]), "r"(a[3]), "r"(b[0]), "r"(b[1]));
}

__device__ __forceinline__ uint32_t pack_h2(float a, float b) {
  __half2 h = __floats2half2_rn(a, b);
  return *(uint32_t*)&h;
}

// ---------------------------------------------------------------------------
// Cast all GEMM operands to fp16 in one streaming launch (float4 granularity).
// ---------------------------------------------------------------------------
__global__ __launch_bounds__(256) void half5(
    const float4* __restrict__ x,  uint2* __restrict__ xh,  int n0,
    const float4* __restrict__ wq, uint2* __restrict__ wqh, int n1,
    const float4* __restrict__ wk, uint2* __restrict__ wkh, int n2,
    const float4* __restrict__ wv, uint2* __restrict__ wvh, int n3,
    const float4* __restrict__ wo, uint2* __restrict__ woh, int n4) {
  int i = blockIdx.x * 256 + threadIdx.x;
  const float4* s; uint2* d;
  if (i < n0) { s = x + i;  d = xh + i; }
  else if ((i -= n0) < n1) { s = wq + i; d = wqh + i; }
  else if ((i -= n1) < n2) { s = wk + i; d = wkh + i; }
  else if ((i -= n2) < n3) { s = wv + i; d = wvh + i; }
  else if ((i -= n3) < n4) { s = wo + i; d = woh + i; }
  else return;
  float4 v = *s;
  *d = make_uint2(pack_h2(v.x, v.y), pack_h2(v.z, v.w));
}

// ---------------------------------------------------------------------------
// fp16 GEMM mainloop: 128x64 block tile, BK=32, 2-stage cp.async.
// 8 warps, warp tile 32x32 (acc = 32 regs) -> 4 CTAs/SM, 32 warps resident.
// smem rows LD=40 halves (conflict-free fragment loads: bank = 4*lr8+lq).
// ---------------------------------------------------------------------------
struct GemmCtx {
  int m0, wm0, wn0, lq, lr8;
};

template <typename Epi>
__device__ __forceinline__ void gemm_body(
    const __half* __restrict__ A, const __half* __restrict__ Bw,
    int K, char* smem, Epi&& epilogue) {
  constexpr int BM = 128, BN = 64, BK = 32, LD = 40;   // LD in halves
  __half* As = (__half*)smem;                 // [2][BM][LD]
  __half* Bs = As + 2 * BM * LD;              // [2][BN][LD]

  const int m0 = blockIdx.y * BM;
  const int t = threadIdx.x;
  const int lane = t & 31, w = t >> 5;
  const int wm0 = (w & 3) * 32;               // 4 m-warps
  const int wn0 = (w >> 2) * 32;              // 2 n-warps
  const int lq = lane & 3;
  const int lr8 = lane >> 2;
  // global loads: A 512 chunks (2/thread), B 256 chunks (1/thread)
  const int r0c = t >> 2, c0c = (t & 3) * 8;

  const __half* Agp = A  + (m0 + r0c) * (long)K + c0c;
  const __half* Bgp = Bw + r0c * (long)K + c0c;      // n0 pre-applied by caller

  uint32_t sA = (uint32_t)__cvta_generic_to_shared(As);
  uint32_t sB = (uint32_t)__cvta_generic_to_shared(Bs);

  auto load_stage = [&](int buf, int k0) {
    uint32_t abase = sA + (uint32_t)(buf * BM * LD) * 2u;
    uint32_t bbase = sB + (uint32_t)(buf * BN * LD) * 2u;
    cp_async16(abase + (uint32_t)(r0c * LD + c0c) * 2u, Agp + k0);
    cp_async16(abase + (uint32_t)((r0c + 64) * LD + c0c) * 2u, Agp + (long)64 * K + k0);
    cp_async16(bbase + (uint32_t)(r0c * LD + c0c) * 2u, Bgp + k0);
    asm volatile("cp.async.commit_group;" ::: "memory");
  };

  float c[2][4][4];
#pragma unroll
  for (int i = 0; i < 2; i++)
#pragma unroll
    for (int j = 0; j < 4; j++)
#pragma unroll
      for (int r = 0; r < 4; r++) c[i][j][r] = 0.f;

  const int NIT = K / BK;
  load_stage(0, 0);

  for (int it = 0; it < NIT; it++) {
    if (it + 1 < NIT) {
      load_stage((it + 1) & 1, (it + 1) * BK);
      asm volatile("cp.async.wait_group 1;" ::: "memory");
    } else {
      asm volatile("cp.async.wait_group 0;" ::: "memory");
    }
    __syncthreads();

    const uint32_t* Ab = (const uint32_t*)(As + (it & 1) * BM * LD);
    const uint32_t* Bb = (const uint32_t*)(Bs + (it & 1) * BN * LD);

#pragma unroll
    for (int ks = 0; ks < 2; ks++) {            // K=16 per step
      const int kh = ks * 8;                    // offset in half2 units
      uint32_t af[2][4], bf[4][2];
#pragma unroll
      for (int mt = 0; mt < 2; mt++) {
        const uint32_t* ap = Ab + (wm0 + mt * 16 + lr8) * (LD / 2) + kh + lq;
        af[mt][0] = ap[0];
        af[mt][1] = ap[8 * (LD / 2)];
        af[mt][2] = ap[4];
        af[mt][3] = ap[8 * (LD / 2) + 4];
      }
#pragma unroll
      for (int nt = 0; nt < 4; nt++) {
        const uint32_t* bp = Bb + (wn0 + nt * 8 + lr8) * (LD / 2) + kh + lq;
        bf[nt][0] = bp[0];
        bf[nt][1] = bp[4];
      }
#pragma unroll
      for (int mt = 0; mt < 2; mt++)
#pragma unroll
        for (int nt = 0; nt < 4; nt++) mma_f16(c[mt][nt], af[mt], bf[nt]);
    }
    __syncthreads();
  }

  GemmCtx ctx{m0, wm0, wn0, lq, lr8};
  epilogue(ctx, c);
}

// ---------------------------------------------------------------------------
// Fused Q/K/V projection. grid = (48, 32):
//   bx  0..31 -> Q n-tile (n0=bx*64)        epilogue: scale -> g_Q fp16 [b,h,s,d]
//   bx 32..39 -> K n-tile (n0=(bx-32)*64)   epilogue: keys fp32 + Kh fp16 [b,g,s,d]
//   bx 40..47 -> V n-tile (n0=(bx-40)*64)   epilogue: values fp32 + Vh fp16 T [b,g,d,s]
// ---------------------------------------------------------------------------
__global__ __launch_bounds__(256, 4) void proj_qkv(
    const __half* __restrict__ x, const __half* __restrict__ Wq,
    const __half* __restrict__ Wk, const __half* __restrict__ Wv,
    __half* __restrict__ Qo, float* __restrict__ keys, float* __restrict__ values,
    __half* __restrict__ Kh, __half* __restrict__ Vh) {
  extern __shared__ char smem[];
  const int bx = blockIdx.x;
  const __half* Bw;
  int n0, which;
  if (bx < 32)      { Bw = Wq; n0 = bx * 64;        which = 0; }
  else if (bx < 40) { Bw = Wk; n0 = (bx - 32) * 64; which = 1; }
  else              { Bw = Wv; n0 = (bx - 40) * 64; which = 2; }

  gemm_body(x, Bw + (long)n0 * kDin, kDin, smem,
    [&](const GemmCtx& g, float c[2][4][4]) {
#pragma unroll
      for (int mt = 0; mt < 2; mt++) {
        int mrow = g.m0 + g.wm0 + mt * 16 + g.lr8;
        int b = mrow >> 11, s = mrow & 2047;
#pragma unroll
        for (int nt = 0; nt < 4; nt++) {
          int coln = n0 + g.wn0 + nt * 8 + g.lq * 2;
          int head = coln >> 6, d = coln & 63;
          if (which == 0) {
            long dst = ((long)(b * kNH + head) * kS + s) * kHD + d;
            *(uint32_t*)(Qo + dst) =
                pack_h2(c[mt][nt][0] * kQScale, c[mt][nt][1] * kQScale);
            *(uint32_t*)(Qo + dst + 8 * kHD) =
                pack_h2(c[mt][nt][2] * kQScale, c[mt][nt][3] * kQScale);
          } else if (which == 1) {
            long dst = ((long)(b * kNKV + head) * kS + s) * kHD + d;
            *(float2*)(keys + dst) = make_float2(c[mt][nt][0], c[mt][nt][1]);
            *(float2*)(keys + dst + 8 * kHD) = make_float2(c[mt][nt][2], c[mt][nt][3]);
            *(uint32_t*)(Kh + dst) = pack_h2(c[mt][nt][0], c[mt][nt][1]);
            *(uint32_t*)(Kh + dst + 8 * kHD) = pack_h2(c[mt][nt][2], c[mt][nt][3]);
          } else {
            long dst = ((long)(b * kNKV + head) * kS + s) * kHD + d;
            *(float2*)(values + dst) = make_float2(c[mt][nt][0], c[mt][nt][1]);
            *(float2*)(values + dst + 8 * kHD) = make_float2(c[mt][nt][2], c[mt][nt][3]);
            // transposed fp16 copy: [b,g,d,s]
            __half* vt = Vh + ((long)(b * kNKV + head) * kHD + d) * kS + s;
            vt[0]      = __float2half(c[mt][nt][0]);
            vt[kS]     = __float2half(c[mt][nt][1]);
            vt[8]      = __float2half(c[mt][nt][2]);
            vt[kS + 8] = __float2half(c[mt][nt][3]);
          }
        }
      }
    });
}

// ---------------------------------------------------------------------------
// O-projection: out[M,N] = Ctx @ Wo^T (fp32 epilogue).
// ---------------------------------------------------------------------------
__global__ __launch_bounds__(256, 4) void gemm_out(
    const __half* __restrict__ A, const __half* __restrict__ Bw,
    float* __restrict__ C, int N, int K) {
  extern __shared__ char smem[];
  const int n0 = blockIdx.x * 64;
  gemm_body(A, Bw + (long)n0 * K, K, smem,
    [&](const GemmCtx& g, float c[2][4][4]) {
#pragma unroll
      for (int mt = 0; mt < 2; mt++) {
        int mrow = g.m0 + g.wm0 + mt * 16 + g.lr8;
#pragma unroll
        for (int nt = 0; nt < 4; nt++) {
          int col = n0 + g.wn0 + nt * 8 + g.lq * 2;
          *(float2*)(C + (long)mrow * N + col) = make_float2(c[mt][nt][0], c[mt][nt][1]);
          *(float2*)(C + (long)(mrow + 8) * N + col) = make_float2(c[mt][nt][2], c[mt][nt][3]);
        }
      }
    });
}

// ---------------------------------------------------------------------------
// Flash attention, fp16 mma.sync m16n8k16, cp.async-pipelined K/V tiles.
// (unchanged from R12)
// ---------------------------------------------------------------------------
__global__ __launch_bounds__(128) void attn_f16(
    const __half* __restrict__ Q, const __half* __restrict__ Kc,
    const __half* __restrict__ Vt, __half* __restrict__ Ctx) {
  constexpr int LD = 72;                       // halves per row
  extern __shared__ char smraw[];
  __half* Qs = (__half*)smraw;                 // [128][LD] q rows, d cols
  __half* Ks = Qs + 128 * LD;                  // [64][LD]  k rows, d cols
  __half* Vs = Ks + 64 * LD;                   // [64][LD]  d rows, k cols (transposed)
  __half* Ps = Vs + 64 * LD;                   // [128][LD] q rows, k cols

  const int qt = gridDim.x - 1 - blockIdx.x;   // heavy blocks first
  const int hb = blockIdx.y;
  const int b = hb >> 5, h = hb & 31, g = h >> 2;
  const int t = threadIdx.x, lane = t & 31, w = t >> 5;
  const int wq0 = w * 32;
  const int lq = lane & 3, lr8 = lane >> 2;
  const int q0 = qt * 128;

  const __half* Qbase = Q  + ((long)(b * kNH + h) * kS + q0) * kHD;
  const __half* Kbase = Kc + (long)(b * kNKV + g) * kS * kHD;
  const __half* Vbase = Vt + (long)(b * kNKV + g) * kHD * kS;   // [d][s]

  const uint32_t sK = (uint32_t)__cvta_generic_to_shared(Ks);
  const uint32_t sV = (uint32_t)__cvta_generic_to_shared(Vs);

  auto issue_K = [&](int k0) {
#pragma unroll
    for (int i = 0; i < 4; i++) {
      int chunk = t + i * 128;
      int r = chunk >> 3, cc = (chunk & 7) * 8;
      cp_async16(sK + (uint32_t)(r * LD + cc) * 2u, Kbase + (long)(k0 + r) * kHD + cc);
    }
    asm volatile("cp.async.commit_group;" ::: "memory");
  };
  auto issue_V = [&](int k0) {
#pragma unroll
    for (int i = 0; i < 4; i++) {
      int chunk = t + i * 128;
      int r = chunk >> 3, cc = (chunk & 7) * 8;   // r = d row, cc = k col
      cp_async16(sV + (uint32_t)(r * LD + cc) * 2u, Vbase + (long)r * kS + k0 + cc);
    }
    asm volatile("cp.async.commit_group;" ::: "memory");
  };

  issue_K(0);
  issue_V(0);

  {  // Q tile: one contiguous 128B row per thread
    const uint4* qp = (const uint4*)(Qbase + (long)t * kHD);
    uint4* dst = (uint4*)(Qs + t * LD);
#pragma unroll
    for (int i = 0; i < 8; i++) dst[i] = qp[i];
  }

  float out[2][8][4];
#pragma unroll
  for (int mt = 0; mt < 2; mt++)
#pragma unroll
    for (int nt = 0; nt < 8; nt++)
#pragma unroll
      for (int r = 0; r < 4; r++) out[mt][nt][r] = 0.f;
  float mrow[2][2] = {{-1e30f, -1e30f}, {-1e30f, -1e30f}};
  float lrow[2][2] = {{0.f, 0.f}, {0.f, 0.f}};

  const uint32_t* Qs32 = (const uint32_t*)Qs;
  const uint32_t* Ks32 = (const uint32_t*)Ks;
  const uint32_t* Vs32 = (const uint32_t*)Vs;
  uint32_t* Ps32 = (uint32_t*)Ps;

  const int nkt = 2 * qt + 2;
  for (int kt = 0; kt < nkt; kt++) {
    const int k0 = kt * 64;

    asm volatile("cp.async.wait_group 1;" ::: "memory");
    __syncthreads();

    // S = Q K^T  (d = 64 -> 4 k16 steps)
    float sc[2][8][4];
#pragma unroll
    for (int mt = 0; mt < 2; mt++)
#pragma unroll
      for (int nt = 0; nt < 8; nt++)
#pragma unroll
        for (int r = 0; r < 4; r++) sc[mt][nt][r] = 0.f;

#pragma unroll
    for (int ks = 0; ks < 4; ks++) {
      const int kh = ks * 8;                       // half2 offset
      uint32_t af[2][4], bf[8][2];
#pragma unroll
      for (int mt = 0; mt < 2; mt++) {
        const uint32_t* ap = Qs32 + (wq0 + mt * 16 + lr8) * (LD / 2) + kh + lq;
        af[mt][0] = ap[0];
        af[mt][1] = ap[8 * (LD / 2)];
        af[mt][2] = ap[4];
        af[mt][3] = ap[8 * (LD / 2) + 4];
      }
#pragma unroll
      for (int nt = 0; nt < 8; nt++) {
        const uint32_t* bp = Ks32 + (nt * 8 + lr8) * (LD / 2) + kh + lq;
        bf[nt][0] = bp[0];
        bf[nt][1] = bp[4];
      }
#pragma unroll
      for (int mt = 0; mt < 2; mt++)
#pragma unroll
        for (int nt = 0; nt < 8; nt++) mma_f16(sc[mt][nt], af[mt], bf[nt]);
    }

    asm volatile("cp.async.wait_group 0;" ::: "memory");
    __syncthreads();
    if (kt + 1 < nkt) issue_K(k0 + 64);

    if (k0 + 63 > q0 + wq0) {
#pragma unroll
      for (int mt = 0; mt < 2; mt++) {
        int r0 = q0 + wq0 + mt * 16 + lr8;
        int r1 = r0 + 8;
#pragma unroll
        for (int nt = 0; nt < 8; nt++) {
          int col = k0 + nt * 8 + 2 * lq;
          if (col > r0)     sc[mt][nt][0] = -1e30f;
          if (col + 1 > r0) sc[mt][nt][1] = -1e30f;
          if (col > r1)     sc[mt][nt][2] = -1e30f;
          if (col + 1 > r1) sc[mt][nt][3] = -1e30f;
        }
      }
    }

    // Online softmax (log2 domain)
#pragma unroll
    for (int mt = 0; mt < 2; mt++) {
      float mx0 = -1e30f, mx1 = -1e30f;
#pragma unroll
      for (int nt = 0; nt < 8; nt++) {
        mx0 = fmaxf(mx0, fmaxf(sc[mt][nt][0], sc[mt][nt][1]));
        mx1 = fmaxf(mx1, fmaxf(sc[mt][nt][2], sc[mt][nt][3]));
      }
      mx0 = fmaxf(mx0, __shfl_xor_sync(0xffffffffu, mx0, 1));
      mx0 = fmaxf(mx0, __shfl_xor_sync(0xffffffffu, mx0, 2));
      mx1 = fmaxf(mx1, __shfl_xor_sync(0xffffffffu, mx1, 1));
      mx1 = fmaxf(mx1, __shfl_xor_sync(0xffffffffu, mx1, 2));

      float mn0 = fmaxf(mrow[mt][0], mx0);
      float mn1 = fmaxf(mrow[mt][1], mx1);
      float e0 = fexp2(mrow[mt][0] - mn0);
      float e1 = fexp2(mrow[mt][1] - mn1);
      mrow[mt][0] = mn0; mrow[mt][1] = mn1;

      float s0 = 0.f, s1 = 0.f;
      uint32_t* pr0 = Ps32 + (wq0 + mt * 16 + lr8) * (LD / 2) + lq;
      uint32_t* pr1 = pr0 + 8 * (LD / 2);
#pragma unroll
      for (int nt = 0; nt < 8; nt++) {
        float p0 = fexp2(sc[mt][nt][0] - mn0);
        float p1 = fexp2(sc[mt][nt][1] - mn0);
        float p2 = fexp2(sc[mt][nt][2] - mn1);
        float p3 = fexp2(sc[mt][nt][3] - mn1);
        uint32_t h01 = pack_h2(p0, p1);
        uint32_t h23 = pack_h2(p2, p3);
        // sum the fp16-rounded values so normalizer matches PV inputs
        __half2 r01 = *(__half2*)&h01, r23 = *(__half2*)&h23;
        s0 += __low2float(r01) + __high2float(r01);
        s1 += __low2float(r23) + __high2float(r23);
        pr0[nt * 4] = h01;
        pr1[nt * 4] = h23;
      }
      s0 += __shfl_xor_sync(0xffffffffu, s0, 1);
      s0 += __shfl_xor_sync(0xffffffffu, s0, 2);
      s1 += __shfl_xor_sync(0xffffffffu, s1, 1);
      s1 += __shfl_xor_sync(0xffffffffu, s1, 2);
      lrow[mt][0] = lrow[mt][0] * e0 + s0;
      lrow[mt][1] = lrow[mt][1] * e1 + s1;
#pragma unroll
      for (int nt = 0; nt < 8; nt++) {
        out[mt][nt][0] *= e0; out[mt][nt][1] *= e0;
        out[mt][nt][2] *= e1; out[mt][nt][3] *= e1;
      }
    }
    __syncwarp();

    // out += P V   (k = key positions, 64 -> 4 k16 steps; V transposed [d][k])
#pragma unroll
    for (int ks = 0; ks < 4; ks++) {
      const int kh = ks * 8;
      uint32_t af[2][4], bf[8][2];
#pragma unroll
      for (int mt = 0; mt < 2; mt++) {
        const uint32_t* ap = Ps32 + (wq0 + mt * 16 + lr8) * (LD / 2) + kh + lq;
        af[mt][0] = ap[0];
        af[mt][1] = ap[8 * (LD / 2)];
        af[mt][2] = ap[4];
        af[mt][3] = ap[8 * (LD / 2) + 4];
      }
#pragma unroll
      for (int nt = 0; nt < 8; nt++) {
        const uint32_t* bp = Vs32 + (nt * 8 + lr8) * (LD / 2) + kh + lq;
        bf[nt][0] = bp[0];
        bf[nt][1] = bp[4];
      }
#pragma unroll
      for (int mt = 0; mt < 2; mt++)
#pragma unroll
        for (int nt = 0; nt < 8; nt++) mma_f16(out[mt][nt], af[mt], bf[nt]);
    }
    __syncthreads();
    if (kt + 1 < nkt) issue_V(k0 + 64);
  }

  // Epilogue: normalize, store ctx as fp16 ([b*s, 2048] for O-proj)
  __half* Cb = Ctx + (long)(b * kS + q0) * kDout + h * kHD;
#pragma unroll
  for (int mt = 0; mt < 2; mt++) {
    int r0 = wq0 + mt * 16 + lr8;
    float inv0 = 1.f / lrow[mt][0];
    float inv1 = 1.f / lrow[mt][1];
#pragma unroll
    for (int nt = 0; nt < 8; nt++) {
      int col = nt * 8 + 2 * lq;
      *(uint32_t*)(Cb + (long)r0 * kDout + col) =
          pack_h2(out[mt][nt][0] * inv0, out[mt][nt][1] * inv0);
      *(uint32_t*)(Cb + (long)(r0 + 8) * kDout + col) =
          pack_h2(out[mt][nt][2] * inv1, out[mt][nt][3] * inv1);
    }
  }
}

// ---------------------------------------------------------------------------
extern "C" void kernel_launch(void* const* d_in, const int* in_sizes, int n_in,
                              void* d_out, int out_size) {
  const float* x  = (const float*)d_in[0];
  const float* Wq = (const float*)d_in[1];
  const float* Wk = (const float*)d_in[2];
  const float* Wv = (const float*)d_in[3];
  const float* Wo = (const float*)d_in[4];

  float* out    = (float*)d_out;                    // [2,2048,2048]
  float* keys   = out + kM * kDout;                 // [2,8,2048,64]
  float* values = keys + kB * kNKV * kS * kHD;      // [2,8,2048,64]

  __half *qb, *kh, *vh, *cb, *xh, *wqh, *wkh, *wvh, *woh;
  cudaGetSymbolAddress((void**)&qb, g_Q);
  cudaGetSymbolAddress((void**)&kh, g_Kh);
  cudaGetSymbolAddress((void**)&vh, g_Vh);
  cudaGetSymbolAddress((void**)&cb, g_Ctx);
  cudaGetSymbolAddress((void**)&xh, g_xh);
  cudaGetSymbolAddress((void**)&wqh, g_Wqh);
  cudaGetSymbolAddress((void**)&wkh, g_Wkh);
  cudaGetSymbolAddress((void**)&wvh, g_Wvh);
  cudaGetSymbolAddress((void**)&woh, g_Woh);

  constexpr int kGemmSmem = 2 * (128 + 64) * 40 * (int)sizeof(__half);   // 30720 B
  constexpr int kAttnSmem = (128 + 64 + 64 + 128) * 72 * (int)sizeof(__half);  // 55296 B
  static bool attr_set = false;
  if (!attr_set) {
    cudaFuncSetAttribute(proj_qkv, cudaFuncAttributeMaxDynamicSharedMemorySize, kGemmSmem);
    cudaFuncSetAttribute(gemm_out, cudaFuncAttributeMaxDynamicSharedMemorySize, kGemmSmem);
    cudaFuncSetAttribute(attn_f16, cudaFuncAttributeMaxDynamicSharedMemorySize, kAttnSmem);
    attr_set = true;
  }

  // 0. Cast all GEMM operands to fp16
  constexpr int n0 = kM * kDin / 4;      // x
  constexpr int n1 = kDout * kDin / 4;   // Wq
  constexpr int n2 = kKV * kDin / 4;     // Wk
  constexpr int n3 = kKV * kDin / 4;     // Wv
  constexpr int n4 = kDin * kDout / 4;   // Wo
  constexpr int ntot = n0 + n1 + n2 + n3 + n4;
  half5<<<(ntot + 255) / 256, 256>>>(
      (const float4*)x,  (uint2*)xh,  n0,
      (const float4*)Wq, (uint2*)wqh, n1,
      (const float4*)Wk, (uint2*)wkh, n2,
      (const float4*)Wv, (uint2*)wvh, n3,
      (const float4*)Wo, (uint2*)woh, n4);

  // 1. Fused Q/K/V projections (48 n-tiles of 64)
  proj_qkv<<<dim3(48, kM / 128), 256, kGemmSmem>>>(
      xh, wqh, wkh, wvh, qb, keys, values, kh, vh);
  // 2. Attention (fp16 tensor cores, cp.async pipelined)
  attn_f16<<<dim3(kS / 128, kB * kNH), dim3(128), kAttnSmem>>>(qb, kh, vh, cb);
  // 3. Output projection
  gemm_out<<<dim3(kDout / 64, kM / 128), 256, kGemmSmem>>>(cb, woh, out, kDout, kDin);
}

// round 14
// speedup vs baseline: 1.0986x; 1.0986x over previous
#include <cuda_runtime.h>
#include <cuda_fp16.h>
#include <cstdint>

// Problem constants
namespace {
constexpr int kB   = 2;
constexpr int kS   = 2048;
constexpr int kDin = 2048;
constexpr int kNH  = 32;
constexpr int kNKV = 8;
constexpr int kHD  = 64;
constexpr int kDout = 2048;           // kNH * kHD
constexpr int kM   = kB * kS;         // 4096 rows
constexpr int kKV  = kNKV * kHD;      // 512
// combined scale: (1/sqrt(64)) * log2(e) so softmax uses raw EX2
constexpr float kQScale = 0.18033688f;
}

// Scratch (static device arrays; cudaMalloc is forbidden)
__device__ __half g_Q[kM * kDout];       // 16 MB (pre-scaled fp16, [b,h,s,d])
__device__ __half g_Kh[kM * kKV];        // 4 MB (fp16, [b,g,s,d])
__device__ __half g_Vh[kM * kKV];        // 4 MB (fp16, TRANSPOSED [b,g,d,s])
__device__ __half g_Ctx[kM * kDout];     // 16 MB (fp16)
__device__ __half g_xh[kM * kDin];       // 16 MB (fp16 inputs/weights)
__device__ __half g_Wqh[kDout * kDin];   // 8 MB
__device__ __half g_Wkh[kKV * kDin];     // 2 MB
__device__ __half g_Wvh[kKV * kDin];     // 2 MB
__device__ __half g_Woh[kDin * kDout];   // 8 MB

__device__ __forceinline__ float fexp2(float x) {
  float y;
  asm("ex2.approx.ftz.f32 %0, %1;" : "=f"(y) : "f"(x));
  return y;
}

__device__ __forceinline__ void cp_async16(uint32_t smem_addr, const void* gptr) {
  asm volatile("cp.async.cg.shared.global [%0], [%1], 16;" :: "r"(smem_addr), "l"(gptr));
}

// fp16 tensor-core MMA: m16n8k16, fp32 accumulate
__device__ __forceinline__ void mma_f16(float* c, const uint32_t* a, const uint32_t* b) {
  asm volatile(
      "mma.sync.aligned.m16n8k16.row.col.f32.f16.f16.f32 "
      "{%0,%1,%2,%3}, {%4,%5,%6,%7}, {%8,%9}, {%0,%1,%2,%3};"
      : "+f"(c[0]), "+f"(c[1]), "+f"(c[2]), "+f"(c[3])
      : "r"(a[0]), "r"(a[1]), "r"(a[2]), "r"(a[3]), "r"(b[0]), "r"(b[1]));
}

__device__ __forceinline__ void ldsm_x4(uint32_t& r0, uint32_t& r1, uint32_t& r2,
                                        uint32_t& r3, uint32_t addr) {
  asm volatile("ldmatrix.sync.aligned.m8n8.x4.shared.b16 {%0,%1,%2,%3}, [%4];"
               : "=r"(r0), "=r"(r1), "=r"(r2), "=r"(r3) : "r"(addr));
}

__device__ __forceinline__ uint32_t pack_h2(float a, float b) {
  __half2 h = __floats2half2_rn(a, b);
  return *(uint32_t*)&h;
}

// ---------------------------------------------------------------------------
// Cast all GEMM operands to fp16 in one streaming launch (float4 granularity).
// ---------------------------------------------------------------------------
__global__ __launch_bounds__(256) void half5(
    const float4* __restrict__ x,  uint2* __restrict__ xh,  int n0,
    const float4* __restrict__ wq, uint2* __restrict__ wqh, int n1,
    const float4* __restrict__ wk, uint2* __restrict__ wkh, int n2,
    const float4* __restrict__ wv, uint2* __restrict__ wvh, int n3,
    const float4* __restrict__ wo, uint2* __restrict__ woh, int n4) {
  int i = blockIdx.x * 256 + threadIdx.x;
  const float4* s; uint2* d;
  if (i < n0) { s = x + i;  d = xh + i; }
  else if ((i -= n0) < n1) { s = wq + i; d = wqh + i; }
  else if ((i -= n1) < n2) { s = wk + i; d = wkh + i; }
  else if ((i -= n2) < n3) { s = wv + i; d = wvh + i; }
  else if ((i -= n3) < n4) { s = wo + i; d = woh + i; }
  else return;
  float4 v = *s;
  *d = make_uint2(pack_h2(v.x, v.y), pack_h2(v.z, v.w));
}

// ---------------------------------------------------------------------------
// fp16 GEMM mainloop: 128x64 block tile, BK=32, 2-stage cp.async.
// 8 warps, warp tile 32x32; fragment loads via ldmatrix.x4 (conflict-free at
// LD=40 halves: 80B row stride covers all 32 banks per 8-row phase).
// ---------------------------------------------------------------------------
struct GemmCtx {
  int m0, wm0, wn0, lq, lr8;
};

template <typename Epi>
__device__ __forceinline__ void gemm_body(
    const __half* __restrict__ A, const __half* __restrict__ Bw,
    int K, char* smem, Epi&& epilogue) {
  constexpr int BM = 128, BN = 64, BK = 32, LD = 40;   // LD in halves
  __half* As = (__half*)smem;                 // [2][BM][LD]
  __half* Bs = As + 2 * BM * LD;              // [2][BN][LD]

  const int m0 = blockIdx.y * BM;
  const int t = threadIdx.x;
  const int lane = t & 31, w = t >> 5;
  const int wm0 = (w & 3) * 32;               // 4 m-warps
  const int wn0 = (w >> 2) * 32;              // 2 n-warps
  const int lq = lane & 3;
  const int lr8 = lane >> 2;
  // ldmatrix lane->address components
  const int la  = lane & 15;                  // A row within 16
  const int lka = (lane >> 4) * 8;            // A k-offset (halves)
  const int lbr = (lane & 7) + ((lane >> 4) * 8);   // B row within 16
  const int lbk = ((lane >> 3) & 1) * 8;            // B k-offset (halves)
  // global loads: A 512 chunks (2/thread), B 256 chunks (1/thread)
  const int r0c = t >> 2, c0c = (t & 3) * 8;

  const __half* Agp = A  + (m0 + r0c) * (long)K + c0c;
  const __half* Bgp = Bw + r0c * (long)K + c0c;      // n0 pre-applied by caller

  uint32_t sA = (uint32_t)__cvta_generic_to_shared(As);
  uint32_t sB = (uint32_t)__cvta_generic_to_shared(Bs);

  auto load_stage = [&](int buf, int k0) {
    uint32_t abase = sA + (uint32_t)(buf * BM * LD) * 2u;
    uint32_t bbase = sB + (uint32_t)(buf * BN * LD) * 2u;
    cp_async16(abase + (uint32_t)(r0c * LD + c0c) * 2u, Agp + k0);
    cp_async16(abase + (uint32_t)((r0c + 64) * LD + c0c) * 2u, Agp + (long)64 * K + k0);
    cp_async16(bbase + (uint32_t)(r0c * LD + c0c) * 2u, Bgp + k0);
    asm volatile("cp.async.commit_group;" ::: "memory");
  };

  float c[2][4][4];
#pragma unroll
  for (int i = 0; i < 2; i++)
#pragma unroll
    for (int j = 0; j < 4; j++)
#pragma unroll
      for (int r = 0; r < 4; r++) c[i][j][r] = 0.f;

  const int NIT = K / BK;
  load_stage(0, 0);

  for (int it = 0; it < NIT; it++) {
    if (it + 1 < NIT) {
      load_stage((it + 1) & 1, (it + 1) * BK);
      asm volatile("cp.async.wait_group 1;" ::: "memory");
    } else {
      asm volatile("cp.async.wait_group 0;" ::: "memory");
    }
    __syncthreads();

    const uint32_t abase = sA + (uint32_t)((it & 1) * BM * LD) * 2u;
    const uint32_t bbase = sB + (uint32_t)((it & 1) * BN * LD) * 2u;

#pragma unroll
    for (int ks = 0; ks < 2; ks++) {            // K=16 per step
      const int kb = ks * 16;                   // halves
      uint32_t af[2][4], bf[4][2];
#pragma unroll
      for (int mt = 0; mt < 2; mt++)
        ldsm_x4(af[mt][0], af[mt][1], af[mt][2], af[mt][3],
                abase + (uint32_t)((wm0 + mt * 16 + la) * LD + kb + lka) * 2u);
#pragma unroll
      for (int j = 0; j < 2; j++) {
        uint32_t r0, r1, r2, r3;
        ldsm_x4(r0, r1, r2, r3,
                bbase + (uint32_t)((wn0 + j * 16 + lbr) * LD + kb + lbk) * 2u);
        bf[2 * j][0] = r0; bf[2 * j][1] = r1;
        bf[2 * j + 1][0] = r2; bf[2 * j + 1][1] = r3;
      }
#pragma unroll
      for (int mt = 0; mt < 2; mt++)
#pragma unroll
        for (int nt = 0; nt < 4; nt++) mma_f16(c[mt][nt], af[mt], bf[nt]);
    }
    __syncthreads();
  }

  GemmCtx ctx{m0, wm0, wn0, lq, lr8};
  epilogue(ctx, c);
}

// ---------------------------------------------------------------------------
// Fused Q/K/V projection. grid = (48, 32):
//   bx  0..31 -> Q n-tile (n0=bx*64)        epilogue: scale -> g_Q fp16 [b,h,s,d]
//   bx 32..39 -> K n-tile (n0=(bx-32)*64)   epilogue: keys fp32 + Kh fp16 [b,g,s,d]
//   bx 40..47 -> V n-tile (n0=(bx-40)*64)   epilogue: values fp32 + Vh fp16 T [b,g,d,s]
// ---------------------------------------------------------------------------
__global__ __launch_bounds__(256, 4) void proj_qkv(
    const __half* __restrict__ x, const __half* __restrict__ Wq,
    const __half* __restrict__ Wk, const __half* __restrict__ Wv,
    __half* __restrict__ Qo, float* __restrict__ keys, float* __restrict__ values,
    __half* __restrict__ Kh, __half* __restrict__ Vh) {
  extern __shared__ char smem[];
  const int bx = blockIdx.x;
  const __half* Bw;
  int n0, which;
  if (bx < 32)      { Bw = Wq; n0 = bx * 64;        which = 0; }
  else if (bx < 40) { Bw = Wk; n0 = (bx - 32) * 64; which = 1; }
  else              { Bw = Wv; n0 = (bx - 40) * 64; which = 2; }

  gemm_body(x, Bw + (long)n0 * kDin, kDin, smem,
    [&](const GemmCtx& g, float c[2][4][4]) {
#pragma unroll
      for (int mt = 0; mt < 2; mt++) {
        int mrow = g.m0 + g.wm0 + mt * 16 + g.lr8;
        int b = mrow >> 11, s = mrow & 2047;
#pragma unroll
        for (int nt = 0; nt < 4; nt++) {
          int coln = n0 + g.wn0 + nt * 8 + g.lq * 2;
          int head = coln >> 6, d = coln & 63;
          if (which == 0) {
            long dst = ((long)(b * kNH + head) * kS + s) * kHD + d;
            *(uint32_t*)(Qo + dst) =
                pack_h2(c[mt][nt][0] * kQScale, c[mt][nt][1] * kQScale);
            *(uint32_t*)(Qo + dst + 8 * kHD) =
                pack_h2(c[mt][nt][2] * kQScale, c[mt][nt][3] * kQScale);
          } else if (which == 1) {
            long dst = ((long)(b * kNKV + head) * kS + s) * kHD + d;
            *(float2*)(keys + dst) = make_float2(c[mt][nt][0], c[mt][nt][1]);
            *(float2*)(keys + dst + 8 * kHD) = make_float2(c[mt][nt][2], c[mt][nt][3]);
            *(uint32_t*)(Kh + dst) = pack_h2(c[mt][nt][0], c[mt][nt][1]);
            *(uint32_t*)(Kh + dst + 8 * kHD) = pack_h2(c[mt][nt][2], c[mt][nt][3]);
          } else {
            long dst = ((long)(b * kNKV + head) * kS + s) * kHD + d;
            *(float2*)(values + dst) = make_float2(c[mt][nt][0], c[mt][nt][1]);
            *(float2*)(values + dst + 8 * kHD) = make_float2(c[mt][nt][2], c[mt][nt][3]);
            // transposed fp16 copy: [b,g,d,s]
            __half* vt = Vh + ((long)(b * kNKV + head) * kHD + d) * kS + s;
            vt[0]      = __float2half(c[mt][nt][0]);
            vt[kS]     = __float2half(c[mt][nt][1]);
            vt[8]      = __float2half(c[mt][nt][2]);
            vt[kS + 8] = __float2half(c[mt][nt][3]);
          }
        }
      }
    });
}

// ---------------------------------------------------------------------------
// O-projection: out[M,N] = Ctx @ Wo^T (fp32 epilogue).
// ---------------------------------------------------------------------------
__global__ __launch_bounds__(256, 4) void gemm_out(
    const __half* __restrict__ A, const __half* __restrict__ Bw,
    float* __restrict__ C, int N, int K) {
  extern __shared__ char smem[];
  const int n0 = blockIdx.x * 64;
  gemm_body(A, Bw + (long)n0 * K, K, smem,
    [&](const GemmCtx& g, float c[2][4][4]) {
#pragma unroll
      for (int mt = 0; mt < 2; mt++) {
        int mrow = g.m0 + g.wm0 + mt * 16 + g.lr8;
#pragma unroll
        for (int nt = 0; nt < 4; nt++) {
          int col = n0 + g.wn0 + nt * 8 + g.lq * 2;
          *(float2*)(C + (long)mrow * N + col) = make_float2(c[mt][nt][0], c[mt][nt][1]);
          *(float2*)(C + (long)(mrow + 8) * N + col) = make_float2(c[mt][nt][2], c[mt][nt][3]);
        }
      }
    });
}

// ---------------------------------------------------------------------------
// Flash attention, fp16 mma.sync m16n8k16 with ldmatrix fragment loads and
// register-resident P (softmax output is already in A-fragment layout).
// Q fp16 [b,h,s,d] (pre-scaled); K fp16 [b,g,s,d]; V fp16 TRANSPOSED [b,g,d,s].
// smem rows LD=72 halves (144B stride -> conflict-free ldmatrix phases).
// ---------------------------------------------------------------------------
__global__ __launch_bounds__(128) void attn_f16(
    const __half* __restrict__ Q, const __half* __restrict__ Kc,
    const __half* __restrict__ Vt, __half* __restrict__ Ctx) {
  constexpr int LD = 72;                       // halves per row
  extern __shared__ char smraw[];
  __half* Qs = (__half*)smraw;                 // [128][LD] q rows, d cols
  __half* Ks = Qs + 128 * LD;                  // [64][LD]  k rows, d cols
  __half* Vs = Ks + 64 * LD;                   // [64][LD]  d rows, k cols (transposed)

  const int qt = gridDim.x - 1 - blockIdx.x;   // heavy blocks first
  const int hb = blockIdx.y;
  const int b = hb >> 5, h = hb & 31, g = h >> 2;
  const int t = threadIdx.x, lane = t & 31, w = t >> 5;
  const int wq0 = w * 32;
  const int lq = lane & 3, lr8 = lane >> 2;
  const int la  = lane & 15;
  const int lka = (lane >> 4) * 8;
  const int lbr = (lane & 7) + ((lane >> 4) * 8);
  const int lbk = ((lane >> 3) & 1) * 8;
  const int q0 = qt * 128;

  const __half* Qbase = Q  + ((long)(b * kNH + h) * kS + q0) * kHD;
  const __half* Kbase = Kc + (long)(b * kNKV + g) * kS * kHD;
  const __half* Vbase = Vt + (long)(b * kNKV + g) * kHD * kS;   // [d][s]

  const uint32_t sQ = (uint32_t)__cvta_generic_to_shared(Qs);
  const uint32_t sK = (uint32_t)__cvta_generic_to_shared(Ks);
  const uint32_t sV = (uint32_t)__cvta_generic_to_shared(Vs);

  auto issue_K = [&](int k0) {
#pragma unroll
    for (int i = 0; i < 4; i++) {
      int chunk = t + i * 128;
      int r = chunk >> 3, cc = (chunk & 7) * 8;
      cp_async16(sK + (uint32_t)(r * LD + cc) * 2u, Kbase + (long)(k0 + r) * kHD + cc);
    }
    asm volatile("cp.async.commit_group;" ::: "memory");
  };
  auto issue_V = [&](int k0) {
#pragma unroll
    for (int i = 0; i < 4; i++) {
      int chunk = t + i * 128;
      int r = chunk >> 3, cc = (chunk & 7) * 8;   // r = d row, cc = k col
      cp_async16(sV + (uint32_t)(r * LD + cc) * 2u, Vbase + (long)r * kS + k0 + cc);
    }
    asm volatile("cp.async.commit_group;" ::: "memory");
  };

  issue_K(0);
  issue_V(0);

  {  // Q tile: one contiguous 128B row per thread
    const uint4* qp = (const uint4*)(Qbase + (long)t * kHD);
    uint4* dst = (uint4*)(Qs + t * LD);
#pragma unroll
    for (int i = 0; i < 8; i++) dst[i] = qp[i];
  }

  float out[2][8][4];
#pragma unroll
  for (int mt = 0; mt < 2; mt++)
#pragma unroll
    for (int nt = 0; nt < 8; nt++)
#pragma unroll
      for (int r = 0; r < 4; r++) out[mt][nt][r] = 0.f;
  float mrow[2][2] = {{-1e30f, -1e30f}, {-1e30f, -1e30f}};
  float lrow[2][2] = {{0.f, 0.f}, {0.f, 0.f}};

  const int nkt = 2 * qt + 2;
  for (int kt = 0; kt < nkt; kt++) {
    const int k0 = kt * 64;

    asm volatile("cp.async.wait_group 1;" ::: "memory");
    __syncthreads();

    // S = Q K^T  (d = 64 -> 4 k16 steps)
    float sc[2][8][4];
#pragma unroll
    for (int mt = 0; mt < 2; mt++)
#pragma unroll
      for (int nt = 0; nt < 8; nt++)
#pragma unroll
        for (int r = 0; r < 4; r++) sc[mt][nt][r] = 0.f;

#pragma unroll
    for (int ks = 0; ks < 4; ks++) {
      const int kb = ks * 16;                      // halves
      uint32_t af[2][4], bf[8][2];
#pragma unroll
      for (int mt = 0; mt < 2; mt++)
        ldsm_x4(af[mt][0], af[mt][1], af[mt][2], af[mt][3],
                sQ + (uint32_t)((wq0 + mt * 16 + la) * LD + kb + lka) * 2u);
#pragma unroll
      for (int j = 0; j < 4; j++) {
        uint32_t r0, r1, r2, r3;
        ldsm_x4(r0, r1, r2, r3,
                sK + (uint32_t)((j * 16 + lbr) * LD + kb + lbk) * 2u);
        bf[2 * j][0] = r0; bf[2 * j][1] = r1;
        bf[2 * j + 1][0] = r2; bf[2 * j + 1][1] = r3;
      }
#pragma unroll
      for (int mt = 0; mt < 2; mt++)
#pragma unroll
        for (int nt = 0; nt < 8; nt++) mma_f16(sc[mt][nt], af[mt], bf[nt]);
    }

    asm volatile("cp.async.wait_group 0;" ::: "memory");
    __syncthreads();
    if (kt + 1 < nkt) issue_K(k0 + 64);

    if (k0 + 63 > q0 + wq0) {
#pragma unroll
      for (int mt = 0; mt < 2; mt++) {
        int r0 = q0 + wq0 + mt * 16 + lr8;
        int r1 = r0 + 8;
#pragma unroll
        for (int nt = 0; nt < 8; nt++) {
          int col = k0 + nt * 8 + 2 * lq;
          if (col > r0)     sc[mt][nt][0] = -1e30f;
          if (col + 1 > r0) sc[mt][nt][1] = -1e30f;
          if (col > r1)     sc[mt][nt][2] = -1e30f;
          if (col + 1 > r1) sc[mt][nt][3] = -1e30f;
        }
      }
    }

    // Online softmax (log2 domain); P packed directly into A-fragment regs
    uint32_t pf[2][8][2];     // [mt][nt] = {rows lr8 pair, rows lr8+8 pair}
#pragma unroll
    for (int mt = 0; mt < 2; mt++) {
      float mx0 = -1e30f, mx1 = -1e30f;
#pragma unroll
      for (int nt = 0; nt < 8; nt++) {
        mx0 = fmaxf(mx0, fmaxf(sc[mt][nt][0], sc[mt][nt][1]));
        mx1 = fmaxf(mx1, fmaxf(sc[mt][nt][2], sc[mt][nt][3]));
      }
      mx0 = fmaxf(mx0, __shfl_xor_sync(0xffffffffu, mx0, 1));
      mx0 = fmaxf(mx0, __shfl_xor_sync(0xffffffffu, mx0, 2));
      mx1 = fmaxf(mx1, __shfl_xor_sync(0xffffffffu, mx1, 1));
      mx1 = fmaxf(mx1, __shfl_xor_sync(0xffffffffu, mx1, 2));

      float mn0 = fmaxf(mrow[mt][0], mx0);
      float mn1 = fmaxf(mrow[mt][1], mx1);
      float e0 = fexp2(mrow[mt][0] - mn0);
      float e1 = fexp2(mrow[mt][1] - mn1);
      mrow[mt][0] = mn0; mrow[mt][1] = mn1;

      float s0 = 0.f, s1 = 0.f;
#pragma unroll
      for (int nt = 0; nt < 8; nt++) {
        float p0 = fexp2(sc[mt][nt][0] - mn0);
        float p1 = fexp2(sc[mt][nt][1] - mn0);
        float p2 = fexp2(sc[mt][nt][2] - mn1);
        float p3 = fexp2(sc[mt][nt][3] - mn1);
        uint32_t h01 = pack_h2(p0, p1);
        uint32_t h23 = pack_h2(p2, p3);
        // sum the fp16-rounded values so normalizer matches PV inputs
        __half2 r01 = *(__half2*)&h01, r23 = *(__half2*)&h23;
        s0 += __low2float(r01) + __high2float(r01);
        s1 += __low2float(r23) + __high2float(r23);
        pf[mt][nt][0] = h01;
        pf[mt][nt][1] = h23;
      }
      s0 += __shfl_xor_sync(0xffffffffu, s0, 1);
      s0 += __shfl_xor_sync(0xffffffffu, s0, 2);
      s1 += __shfl_xor_sync(0xffffffffu, s1, 1);
      s1 += __shfl_xor_sync(0xffffffffu, s1, 2);
      lrow[mt][0] = lrow[mt][0] * e0 + s0;
      lrow[mt][1] = lrow[mt][1] * e1 + s1;
#pragma unroll
      for (int nt = 0; nt < 8; nt++) {
        out[mt][nt][0] *= e0; out[mt][nt][1] *= e0;
        out[mt][nt][2] *= e1; out[mt][nt][3] *= e1;
      }
    }

    // out += P V   (P in registers; V via ldmatrix from transposed tile)
#pragma unroll
    for (int ks = 0; ks < 4; ks++) {
      const int kb = ks * 16;
      uint32_t af[2][4], bf[8][2];
#pragma unroll
      for (int mt = 0; mt < 2; mt++) {
        af[mt][0] = pf[mt][2 * ks][0];
        af[mt][1] = pf[mt][2 * ks][1];
        af[mt][2] = pf[mt][2 * ks + 1][0];
        af[mt][3] = pf[mt][2 * ks + 1][1];
      }
#pragma unroll
      for (int j = 0; j < 4; j++) {
        uint32_t r0, r1, r2, r3;
        ldsm_x4(r0, r1, r2, r3,
                sV + (uint32_t)((j * 16 + lbr) * LD + kb + lbk) * 2u);
        bf[2 * j][0] = r0; bf[2 * j][1] = r1;
        bf[2 * j + 1][0] = r2; bf[2 * j + 1][1] = r3;
      }
#pragma unroll
      for (int mt = 0; mt < 2; mt++)
#pragma unroll
        for (int nt = 0; nt < 8; nt++) mma_f16(out[mt][nt], af[mt], bf[nt]);
    }
    __syncthreads();
    if (kt + 1 < nkt) issue_V(k0 + 64);
  }

  // Epilogue: normalize, store ctx as fp16 ([b*s, 2048] for O-proj)
  __half* Cb = Ctx + (long)(b * kS + q0) * kDout + h * kHD;
#pragma unroll
  for (int mt = 0; mt < 2; mt++) {
    int r0 = wq0 + mt * 16 + lr8;
    float inv0 = 1.f / lrow[mt][0];
    float inv1 = 1.f / lrow[mt][1];
#pragma unroll
    for (int nt = 0; nt < 8; nt++) {
      int col = nt * 8 + 2 * lq;
      *(uint32_t*)(Cb + (long)r0 * kDout + col) =
          pack_h2(out[mt][nt][0] * inv0, out[mt][nt][1] * inv0);
      *(uint32_t*)(Cb + (long)(r0 + 8) * kDout + col) =
          pack_h2(out[mt][nt][2] * inv1, out[mt][nt][3] * inv1);
    }
  }
}

// ---------------------------------------------------------------------------
extern "C" void kernel_launch(void* const* d_in, const int* in_sizes, int n_in,
                              void* d_out, int out_size) {
  const float* x  = (const float*)d_in[0];
  const float* Wq = (const float*)d_in[1];
  const float* Wk = (const float*)d_in[2];
  const float* Wv = (const float*)d_in[3];
  const float* Wo = (const float*)d_in[4];

  float* out    = (float*)d_out;                    // [2,2048,2048]
  float* keys   = out + kM * kDout;                 // [2,8,2048,64]
  float* values = keys + kB * kNKV * kS * kHD;      // [2,8,2048,64]

  __half *qb, *kh, *vh, *cb, *xh, *wqh, *wkh, *wvh, *woh;
  cudaGetSymbolAddress((void**)&qb, g_Q);
  cudaGetSymbolAddress((void**)&kh, g_Kh);
  cudaGetSymbolAddress((void**)&vh, g_Vh);
  cudaGetSymbolAddress((void**)&cb, g_Ctx);
  cudaGetSymbolAddress((void**)&xh, g_xh);
  cudaGetSymbolAddress((void**)&wqh, g_Wqh);
  cudaGetSymbolAddress((void**)&wkh, g_Wkh);
  cudaGetSymbolAddress((void**)&wvh, g_Wvh);
  cudaGetSymbolAddress((void**)&woh, g_Woh);

  constexpr int kGemmSmem = 2 * (128 + 64) * 40 * (int)sizeof(__half);   // 30720 B
  constexpr int kAttnSmem = (128 + 64 + 64) * 72 * (int)sizeof(__half);  // 36864 B
  static bool attr_set = false;
  if (!attr_set) {
    cudaFuncSetAttribute(proj_qkv, cudaFuncAttributeMaxDynamicSharedMemorySize, kGemmSmem);
    cudaFuncSetAttribute(gemm_out, cudaFuncAttributeMaxDynamicSharedMemorySize, kGemmSmem);
    cudaFuncSetAttribute(attn_f16, cudaFuncAttributeMaxDynamicSharedMemorySize, kAttnSmem);
    attr_set = true;
  }

  // 0. Cast all GEMM operands to fp16
  constexpr int n0 = kM * kDin / 4;      // x
  constexpr int n1 = kDout * kDin / 4;   // Wq
  constexpr int n2 = kKV * kDin / 4;     // Wk
  constexpr int n3 = kKV * kDin / 4;     // Wv
  constexpr int n4 = kDin * kDout / 4;   // Wo
  constexpr int ntot = n0 + n1 + n2 + n3 + n4;
  half5<<<(ntot + 255) / 256, 256>>>(
      (const float4*)x,  (uint2*)xh,  n0,
      (const float4*)Wq, (uint2*)wqh, n1,
      (const float4*)Wk, (uint2*)wkh, n2,
      (const float4*)Wv, (uint2*)wvh, n3,
      (const float4*)Wo, (uint2*)woh, n4);

  // 1. Fused Q/K/V projections (48 n-tiles of 64)
  proj_qkv<<<dim3(48, kM / 128), 256, kGemmSmem>>>(
      xh, wqh, wkh, wvh, qb, keys, values, kh, vh);
  // 2. Attention (fp16 tensor cores, ldmatrix + register P)
  attn_f16<<<dim3(kS / 128, kB * kNH), dim3(128), kAttnSmem>>>(qb, kh, vh, cb);
  // 3. Output projection
  gemm_out<<<dim3(kDout / 64, kM / 128), 256, kGemmSmem>>>(cb, woh, out, kDout, kDin);
}